// round 14
// baseline (speedup 1.0000x reference)
#include <cuda_runtime.h>
#include <cuda_bf16.h>
#include <math.h>

// Problem constants (fixed by reference)
#define B_      16
#define T_      8192
#define D_      512
#define H_      8
#define HD_     64
#define K_      4
#define TR_     8                 // rows per tile
#define TB_     (T_/TR_)          // 1024 tiles per batch
#define NTHR_   256
#define NBUF_   4

// One balanced wave at 2 CTAs/SM on 152 SMs: 304 = 16 x 19
#define GB_     19
#define G_      (B_*GB_)

// Per-warp buffer: 8 rows x 68 floats (64 data + 4 pad) + 8 mask ints.
#define WSTR_    68
#define WBUF_F   (TR_*WSTR_ + 8)          // 552 floats = 2208 B
#define SM_WARPS_F (H_*NBUF_*WBUF_F)      // 17664 floats
#define SM_P_F   (H_*TR_*K_)              // 256 floats
#define SMEM_BYTES ((SM_WARPS_F + SM_P_F)*4)   // 71680 B

// ---------------- device scratch (no allocations allowed) ----------------
__device__ __align__(16) float g_pool[B_*K_*D_];     // atomic accumulators
__device__ __align__(16) float g_lsum[B_*K_*H_];     // atomic denominators
__device__ int   g_ctr[B_];                          // per-batch completion

// ---------------- packed fp32x2 FMA (Blackwell) ----------------
union F2U { float2 f; unsigned long long u; };
__device__ __forceinline__ float2 ffma2(float2 a, float2 b, float2 c) {
    F2U A, Bv, C, Dv;
    A.f = a; Bv.f = b; C.f = c;
    asm("fma.rn.f32x2 %0, %1, %2, %3;" : "=l"(Dv.u) : "l"(A.u), "l"(Bv.u), "l"(C.u));
    return Dv.f;
}

#define CP_COMMIT() asm volatile("cp.async.commit_group;")
#define CP_WAIT2()  asm volatile("cp.async.wait_group 2;")
#define CP_WAIT1()  asm volatile("cp.async.wait_group 1;")
#define CP_WAIT0()  asm volatile("cp.async.wait_group 0;")

__device__ __forceinline__ void cp16(float* dst_sh, const void* src) {
    unsigned d = (unsigned)__cvta_generic_to_shared(dst_sh);
    asm volatile("cp.async.cg.shared.global [%0], [%1], 16;" :: "r"(d), "l"(src));
}

// Per-warp: copy this head's 64-float slice of 8 rows (+ 8 mask ints).
__device__ __forceinline__ void issue_wtile(const float* __restrict__ src,
                                            float* __restrict__ dst,
                                            const int* __restrict__ msrc,
                                            int lane)
{
    #pragma unroll
    for (int i = 0; i < 4; i++) {
        int cchunk = lane + 32 * i;          // 0..127
        int row = cchunk >> 4;               // 0..7
        int ch  = cchunk & 15;               // 0..15
        cp16(dst + row * WSTR_ + ch * 4, src + (long)row * D_ + ch * 4);
    }
    if (lane < 2)
        cp16(dst + TR_ * WSTR_ + lane * 4, msrc + lane * 4);
}

// ======================================================================
// Kernel: warp-autonomous attention pooling (R10 mainloop, proven best)
// + FUSED epilogue: the last CTA of each batch (atomic counter) computes
// that batch's 4 output rows (normalize + linear projection).
// ======================================================================
__global__ void __launch_bounds__(NTHR_, 2)
attn_main(const float* __restrict__ x, const int* __restrict__ mask,
          const float* __restrict__ queries,
          const float* __restrict__ w_out, const float* __restrict__ b_out,
          float* __restrict__ out)
{
    extern __shared__ float sm[];
    float* p_sh = sm + SM_WARPS_F;             // [H][8][K]
    __shared__ int sflag;

    const int c    = blockIdx.x;
    const int tid  = threadIdx.x;
    const int w    = tid >> 5;                 // warp == head
    const int lane = tid & 31;
    const int row  = lane >> 2;                // 0..7
    const int k_ln = lane & 3;                 // this lane's query index

    const int b = c / GB_;
    const int j = c % GB_;
    const int tstart = (j * TB_) / GB_;
    const int ntiles = ((j + 1) * TB_) / GB_ - tstart;   // ~53-54, always >= 4

    const float* xw = x + ((long)b * T_ + (long)tstart * TR_) * D_ + w * HD_;
    const int*   mw = mask + (long)b * T_ + tstart * TR_;
    float* wb  = sm + w * NBUF_ * WBUF_F;      // private buffers
    float* p_w = p_sh + w * TR_ * K_;

    // ---- q -> registers: this lane's query row, this head's 64 dims ----
    float4 q[16];
    const float4* qsrc = reinterpret_cast<const float4*>(
                             queries + (long)k_ln * D_ + w * HD_);
    #pragma unroll
    for (int i = 0; i < 16; i++) q[i] = __ldg(qsrc + i);

    float  l = 0.f;
    float2 acc[K_];
    #pragma unroll
    for (int k = 0; k < K_; k++) acc[k] = make_float2(0.f, 0.f);

    // prologue: 3 tiles in flight
    #pragma unroll
    for (int i = 0; i < 3; i++) {
        issue_wtile(xw + (long)i * TR_ * D_, wb + i * WBUF_F, mw + i * TR_, lane);
        CP_COMMIT();
    }

    for (int tl = 0; tl < ntiles; tl++) {
        int pend = ntiles - (tl + 1); if (pend > 2) pend = 2;
        if (pend == 2) CP_WAIT2(); else if (pend == 1) CP_WAIT1(); else CP_WAIT0();
        __syncwarp();

        float* tile = wb + (tl & (NBUF_-1)) * WBUF_F;
        const int* msk = (const int*)(tile + TR_ * WSTR_);

        // ---- phase 1: 64-dim dot with 4 independent partial sums ----
        float2 s0 = make_float2(0.f, 0.f), s1 = make_float2(0.f, 0.f);
        float2 s2 = make_float2(0.f, 0.f), s3 = make_float2(0.f, 0.f);
        const float* vrow = tile + row * WSTR_;
        #pragma unroll
        for (int g = 0; g < 4; g++) {          // 4 groups of 4 float4 chunks
            float4 va = *reinterpret_cast<const float4*>(vrow + (g*4+0) * 4);
            float4 vb = *reinterpret_cast<const float4*>(vrow + (g*4+1) * 4);
            float4 vc = *reinterpret_cast<const float4*>(vrow + (g*4+2) * 4);
            float4 vd = *reinterpret_cast<const float4*>(vrow + (g*4+3) * 4);
            s0 = ffma2(make_float2(va.x, va.y), make_float2(q[g*4+0].x, q[g*4+0].y), s0);
            s1 = ffma2(make_float2(va.z, va.w), make_float2(q[g*4+0].z, q[g*4+0].w), s1);
            s2 = ffma2(make_float2(vb.x, vb.y), make_float2(q[g*4+1].x, q[g*4+1].y), s2);
            s3 = ffma2(make_float2(vb.z, vb.w), make_float2(q[g*4+1].z, q[g*4+1].w), s3);
            s0 = ffma2(make_float2(vc.x, vc.y), make_float2(q[g*4+2].x, q[g*4+2].y), s0);
            s1 = ffma2(make_float2(vc.z, vc.w), make_float2(q[g*4+2].z, q[g*4+2].w), s1);
            s2 = ffma2(make_float2(vd.x, vd.y), make_float2(q[g*4+3].x, q[g*4+3].y), s2);
            s3 = ffma2(make_float2(vd.z, vd.w), make_float2(q[g*4+3].z, q[g*4+3].w), s3);
        }
        float2 t01 = make_float2(s0.x + s1.x, s0.y + s1.y);
        float2 t23 = make_float2(s2.x + s3.x, s2.y + s3.y);
        float  v   = (t01.x + t23.x) + (t01.y + t23.y);
        float p = (msk[row] == 0) ? 0.f : __expf(v * 0.125f);
        l += p;
        p_w[lane] = p;                         // [row][k] contiguous, conflict-free
        __syncwarp();

        // ---- phase 2: lane owns d = {2*lane, 2*lane+1} of this head ----
        const float* base2 = tile + 2 * lane;
        #pragma unroll
        for (int t = 0; t < TR_; t++) {
            float2 v2 = *reinterpret_cast<const float2*>(base2 + t * WSTR_);
            float4 p4 = *reinterpret_cast<const float4*>(p_w + t * K_);
            acc[0] = ffma2(v2, make_float2(p4.x, p4.x), acc[0]);
            acc[1] = ffma2(v2, make_float2(p4.y, p4.y), acc[1]);
            acc[2] = ffma2(v2, make_float2(p4.z, p4.z), acc[2]);
            acc[3] = ffma2(v2, make_float2(p4.w, p4.w), acc[3]);
        }
        __syncwarp();                          // lanes done reading buffer & p_w

        if (tl + 3 < ntiles) {
            issue_wtile(xw + (long)(tl + 3) * TR_ * D_,
                        wb + ((tl + 3) & (NBUF_-1)) * WBUF_F,
                        mw + (tl + 3) * TR_, lane);
            CP_COMMIT();
        }
    }

    // ---- reduce l over rows (lanes sharing k = lane&3) ----
    l += __shfl_xor_sync(0xffffffffu, l, 4);
    l += __shfl_xor_sync(0xffffffffu, l, 8);
    l += __shfl_xor_sync(0xffffffffu, l, 16);

    // ---- atomic tail: plain sums across CTAs (m = 0 everywhere) ----
    if (lane < K_)
        atomicAdd(&g_lsum[((long)b * K_ + lane) * H_ + w], l);
    #pragma unroll
    for (int k = 0; k < K_; k++) {
        float* dst = &g_pool[((long)b * K_ + k) * D_ + w * HD_ + 2 * lane];
        atomicAdd(dst,     acc[k].x);
        atomicAdd(dst + 1, acc[k].y);
    }

    // ================= fused epilogue (last CTA of this batch) ==========
    __threadfence();                 // publish this CTA's atomics (release)
    __syncthreads();
    if (tid == 0) sflag = (atomicAdd(&g_ctr[b], 1) == GB_ - 1);
    __syncthreads();
    if (!sflag) return;
    __threadfence();                 // acquire: see all 19 CTAs' atomics

    // rows b*K .. b*K+3; 4 rows x 64 jgroups = 256 (r, jg) warp-tasks,
    // 8 warps x 32 iterations. Lane-major coalesced loads (R13 pattern).
    for (int idx = w; idx < 4 * 64; idx += H_) {
        const int rl = idx & 3;              // row local 0..3
        const int jg = idx >> 2;             // 0..63
        const int r  = b * K_ + rl;

        const float4* pr = reinterpret_cast<const float4*>(g_pool + (long)r * D_);
        float4 pv[4];
        #pragma unroll
        for (int i = 0; i < 4; i++) {
            int i4 = i * 32 + lane;          // float4 index; dim = i4*4
            float inv = 1.f / __ldcg(&g_lsum[r * H_ + (i4 >> 4)]);
            float4 v = __ldcg(&pr[i4]);
            pv[i] = make_float4(v.x * inv, v.y * inv, v.z * inv, v.w * inv);
        }

        float my = 0.f;                      // lane j0 keeps output j0's total
        #pragma unroll
        for (int j0 = 0; j0 < 8; j0++) {
            const float4* wr = reinterpret_cast<const float4*>(
                                   w_out + (long)(jg * 8 + j0) * D_);
            float2 s = make_float2(0.f, 0.f);
            #pragma unroll
            for (int i = 0; i < 4; i++) {
                float4 wv = __ldg(&wr[i * 32 + lane]);
                s = ffma2(make_float2(wv.x, wv.y), make_float2(pv[i].x, pv[i].y), s);
                s = ffma2(make_float2(wv.z, wv.w), make_float2(pv[i].z, pv[i].w), s);
            }
            float t = s.x + s.y;
            #pragma unroll
            for (int off = 16; off > 0; off >>= 1)
                t += __shfl_xor_sync(0xffffffffu, t, off);
            if (lane == j0) my = t;
        }

        if (lane < 8) {
            int jj = jg * 8 + lane;
            out[(long)r * D_ + jj] = b_out[jj] + my;
        }
    }
}

// ======================================================================
extern "C" void kernel_launch(void* const* d_in, const int* in_sizes, int n_in,
                              void* d_out, int out_size)
{
    const float* x       = (const float*)d_in[0];
    const int*   mask    = (const int*)  d_in[1];
    const float* queries = (const float*)d_in[2];
    const float* w_out   = (const float*)d_in[3];
    const float* b_out   = (const float*)d_in[4];
    float* out = (float*)d_out;

    cudaFuncSetAttribute((const void*)attn_main,
                         cudaFuncAttributeMaxDynamicSharedMemorySize, SMEM_BYTES);

    // zero accumulators + per-batch counters via graph memset nodes
    void* p_pool = nullptr; void* p_lsum = nullptr; void* p_ctr = nullptr;
    cudaGetSymbolAddress(&p_pool, g_pool);
    cudaGetSymbolAddress(&p_lsum, g_lsum);
    cudaGetSymbolAddress(&p_ctr,  g_ctr);
    cudaMemsetAsync(p_pool, 0, sizeof(float) * B_ * K_ * D_);
    cudaMemsetAsync(p_lsum, 0, sizeof(float) * B_ * K_ * H_);
    cudaMemsetAsync(p_ctr,  0, sizeof(int) * B_);

    attn_main<<<G_, NTHR_, SMEM_BYTES>>>(x, mask, queries, w_out, b_out, out);
}

// round 15
// speedup vs baseline: 2.1827x; 2.1827x over previous
#include <cuda_runtime.h>
#include <cuda_bf16.h>
#include <math.h>

// Problem constants (fixed by reference)
#define B_      16
#define T_      8192
#define D_      512
#define H_      8
#define HD_     64
#define K_      4
#define TR_     8                 // rows per tile
#define TB_     (T_/TR_)          // 1024 tiles per batch
#define NTHR_   256
#define NBUF_   4

// One balanced wave at 2 CTAs/SM on 152 SMs: 304 = 16 x 19
#define GB_     19
#define G_      (B_*GB_)

// Per-warp buffer: 8 rows x 68 floats (64 data + 4 pad) + 8 mask ints.
#define WSTR_    68
#define WBUF_F   (TR_*WSTR_ + 8)          // 552 floats = 2208 B
#define SM_WARPS_F (H_*NBUF_*WBUF_F)      // 17664 floats
#define SM_P_F   (H_*TR_*K_)              // 256 floats
#define SMEM_BYTES ((SM_WARPS_F + SM_P_F)*4)   // 71680 B

// ---------------- device scratch (no allocations allowed) ----------------
__device__ __align__(16) float g_pool[B_*K_*D_];     // atomic accumulators
__device__ __align__(16) float g_lsum[B_*K_*H_];     // atomic denominators

// ---------------- packed fp32x2 FMA (Blackwell) ----------------
union F2U { float2 f; unsigned long long u; };
__device__ __forceinline__ float2 ffma2(float2 a, float2 b, float2 c) {
    F2U A, Bv, C, Dv;
    A.f = a; Bv.f = b; C.f = c;
    asm("fma.rn.f32x2 %0, %1, %2, %3;" : "=l"(Dv.u) : "l"(A.u), "l"(Bv.u), "l"(C.u));
    return Dv.f;
}

#define CP_COMMIT() asm volatile("cp.async.commit_group;")
#define CP_WAIT2()  asm volatile("cp.async.wait_group 2;")
#define CP_WAIT1()  asm volatile("cp.async.wait_group 1;")
#define CP_WAIT0()  asm volatile("cp.async.wait_group 0;")

__device__ __forceinline__ void cp16(float* dst_sh, const void* src) {
    unsigned d = (unsigned)__cvta_generic_to_shared(dst_sh);
    asm volatile("cp.async.cg.shared.global [%0], [%1], 16;" :: "r"(d), "l"(src));
}

// Per-warp: copy this head's 64-float slice of 8 rows (+ 8 mask ints).
__device__ __forceinline__ void issue_wtile(const float* __restrict__ src,
                                            float* __restrict__ dst,
                                            const int* __restrict__ msrc,
                                            int lane)
{
    #pragma unroll
    for (int i = 0; i < 4; i++) {
        int cchunk = lane + 32 * i;          // 0..127
        int row = cchunk >> 4;               // 0..7
        int ch  = cchunk & 15;               // 0..15
        cp16(dst + row * WSTR_ + ch * 4, src + (long)row * D_ + ch * 4);
    }
    if (lane < 2)
        cp16(dst + TR_ * WSTR_ + lane * 4, msrc + lane * 4);
}

// ======================================================================
// Kernel 1 (R10/R13 proven-best, UNTOUCHED): warp-autonomous attention
// pooling, fixed softmax shift (m=0). lane = (row, k), q register-
// resident, NBUF=4, 4-way ILP dot product, atomic tail.
// ======================================================================
__global__ void __launch_bounds__(NTHR_, 2)
attn_main(const float* __restrict__ x, const int* __restrict__ mask,
          const float* __restrict__ queries)
{
    extern __shared__ float sm[];
    float* p_sh = sm + SM_WARPS_F;             // [H][8][K]

    const int c    = blockIdx.x;
    const int tid  = threadIdx.x;
    const int w    = tid >> 5;                 // warp == head
    const int lane = tid & 31;
    const int row  = lane >> 2;                // 0..7
    const int k_ln = lane & 3;                 // this lane's query index

    const int b = c / GB_;
    const int j = c % GB_;
    const int tstart = (j * TB_) / GB_;
    const int ntiles = ((j + 1) * TB_) / GB_ - tstart;   // ~53-54, always >= 4

    const float* xw = x + ((long)b * T_ + (long)tstart * TR_) * D_ + w * HD_;
    const int*   mw = mask + (long)b * T_ + tstart * TR_;
    float* wb  = sm + w * NBUF_ * WBUF_F;      // private buffers
    float* p_w = p_sh + w * TR_ * K_;

    // ---- q -> registers: this lane's query row, this head's 64 dims ----
    float4 q[16];
    const float4* qsrc = reinterpret_cast<const float4*>(
                             queries + (long)k_ln * D_ + w * HD_);
    #pragma unroll
    for (int i = 0; i < 16; i++) q[i] = __ldg(qsrc + i);

    float  l = 0.f;
    float2 acc[K_];
    #pragma unroll
    for (int k = 0; k < K_; k++) acc[k] = make_float2(0.f, 0.f);

    // prologue: 3 tiles in flight
    #pragma unroll
    for (int i = 0; i < 3; i++) {
        issue_wtile(xw + (long)i * TR_ * D_, wb + i * WBUF_F, mw + i * TR_, lane);
        CP_COMMIT();
    }

    for (int tl = 0; tl < ntiles; tl++) {
        int pend = ntiles - (tl + 1); if (pend > 2) pend = 2;
        if (pend == 2) CP_WAIT2(); else if (pend == 1) CP_WAIT1(); else CP_WAIT0();
        __syncwarp();

        float* tile = wb + (tl & (NBUF_-1)) * WBUF_F;
        const int* msk = (const int*)(tile + TR_ * WSTR_);

        // ---- phase 1: 64-dim dot with 4 independent partial sums ----
        float2 s0 = make_float2(0.f, 0.f), s1 = make_float2(0.f, 0.f);
        float2 s2 = make_float2(0.f, 0.f), s3 = make_float2(0.f, 0.f);
        const float* vrow = tile + row * WSTR_;
        #pragma unroll
        for (int g = 0; g < 4; g++) {          // 4 groups of 4 float4 chunks
            float4 va = *reinterpret_cast<const float4*>(vrow + (g*4+0) * 4);
            float4 vb = *reinterpret_cast<const float4*>(vrow + (g*4+1) * 4);
            float4 vc = *reinterpret_cast<const float4*>(vrow + (g*4+2) * 4);
            float4 vd = *reinterpret_cast<const float4*>(vrow + (g*4+3) * 4);
            s0 = ffma2(make_float2(va.x, va.y), make_float2(q[g*4+0].x, q[g*4+0].y), s0);
            s1 = ffma2(make_float2(va.z, va.w), make_float2(q[g*4+0].z, q[g*4+0].w), s1);
            s2 = ffma2(make_float2(vb.x, vb.y), make_float2(q[g*4+1].x, q[g*4+1].y), s2);
            s3 = ffma2(make_float2(vb.z, vb.w), make_float2(q[g*4+1].z, q[g*4+1].w), s3);
            s0 = ffma2(make_float2(vc.x, vc.y), make_float2(q[g*4+2].x, q[g*4+2].y), s0);
            s1 = ffma2(make_float2(vc.z, vc.w), make_float2(q[g*4+2].z, q[g*4+2].w), s1);
            s2 = ffma2(make_float2(vd.x, vd.y), make_float2(q[g*4+3].x, q[g*4+3].y), s2);
            s3 = ffma2(make_float2(vd.z, vd.w), make_float2(q[g*4+3].z, q[g*4+3].w), s3);
        }
        float2 t01 = make_float2(s0.x + s1.x, s0.y + s1.y);
        float2 t23 = make_float2(s2.x + s3.x, s2.y + s3.y);
        float  v   = (t01.x + t23.x) + (t01.y + t23.y);
        float p = (msk[row] == 0) ? 0.f : __expf(v * 0.125f);
        l += p;
        p_w[lane] = p;                         // [row][k] contiguous, conflict-free
        __syncwarp();

        // ---- phase 2: lane owns d = {2*lane, 2*lane+1} of this head ----
        const float* base2 = tile + 2 * lane;
        #pragma unroll
        for (int t = 0; t < TR_; t++) {
            float2 v2 = *reinterpret_cast<const float2*>(base2 + t * WSTR_);
            float4 p4 = *reinterpret_cast<const float4*>(p_w + t * K_);
            acc[0] = ffma2(v2, make_float2(p4.x, p4.x), acc[0]);
            acc[1] = ffma2(v2, make_float2(p4.y, p4.y), acc[1]);
            acc[2] = ffma2(v2, make_float2(p4.z, p4.z), acc[2]);
            acc[3] = ffma2(v2, make_float2(p4.w, p4.w), acc[3]);
        }
        __syncwarp();                          // lanes done reading buffer & p_w

        if (tl + 3 < ntiles) {
            issue_wtile(xw + (long)(tl + 3) * TR_ * D_,
                        wb + ((tl + 3) & (NBUF_-1)) * WBUF_F,
                        mw + (tl + 3) * TR_, lane);
            CP_COMMIT();
        }
    }

    // ---- reduce l over rows (lanes sharing k = lane&3) ----
    l += __shfl_xor_sync(0xffffffffu, l, 4);
    l += __shfl_xor_sync(0xffffffffu, l, 8);
    l += __shfl_xor_sync(0xffffffffu, l, 16);

    // ---- atomic tail: plain sums across CTAs (m = 0 everywhere) ----
    if (lane < K_)
        atomicAdd(&g_lsum[((long)b * K_ + lane) * H_ + w], l);
    #pragma unroll
    for (int k = 0; k < K_; k++) {
        float* dst = &g_pool[((long)b * K_ + k) * D_ + w * HD_ + 2 * lane];
        atomicAdd(dst,     acc[k].x);
        atomicAdd(dst + 1, acc[k].y);
    }
}

// ======================================================================
// Kernel 2: normalize + linear projection, warp-per-(row-PAIR, 8 outputs).
// 2048 warps (256 blocks). Each warp reads the 8 w_out rows ONCE and
// applies them to TWO pooled rows -> w L2 traffic halved vs R13.
// All loads lane-major coalesced; butterfly reduce; lanes 0..7 write.
// ======================================================================
__global__ void __launch_bounds__(256)
epi_k(const float* __restrict__ w_out, const float* __restrict__ b_out,
      float* __restrict__ out)
{
    const int gw   = blockIdx.x * 8 + (threadIdx.x >> 5);   // 0..2047
    const int lane = threadIdx.x & 31;
    const int jg   = gw >> 5;               // 0..63
    const int rp   = gw & 31;               // row pair: rows 2rp, 2rp+1
    const int r0   = rp * 2, r1 = rp * 2 + 1;

    // ---- load + normalize both pooled rows, lane-major coalesced ----
    const float4* pr0 = reinterpret_cast<const float4*>(g_pool + (long)r0 * D_);
    const float4* pr1 = reinterpret_cast<const float4*>(g_pool + (long)r1 * D_);
    float4 pv0[4], pv1[4];
    #pragma unroll
    for (int i = 0; i < 4; i++) {
        int idx = i * 32 + lane;             // float4 index; dim = idx*4
        int h   = idx >> 4;
        float inv0 = 1.f / g_lsum[r0 * H_ + h];
        float inv1 = 1.f / g_lsum[r1 * H_ + h];
        float4 v0 = pr0[idx];
        float4 v1 = pr1[idx];
        pv0[i] = make_float4(v0.x*inv0, v0.y*inv0, v0.z*inv0, v0.w*inv0);
        pv1[i] = make_float4(v1.x*inv1, v1.y*inv1, v1.z*inv1, v1.w*inv1);
    }

    float my0 = 0.f, my1 = 0.f;              // lane j0 keeps outputs' totals
    #pragma unroll
    for (int j0 = 0; j0 < 8; j0++) {
        const float4* wr = reinterpret_cast<const float4*>(
                               w_out + (long)(jg * 8 + j0) * D_);
        float2 sA = make_float2(0.f, 0.f), sB = make_float2(0.f, 0.f);
        #pragma unroll
        for (int i = 0; i < 4; i++) {
            float4 wv = wr[i * 32 + lane];
            sA = ffma2(make_float2(wv.x, wv.y), make_float2(pv0[i].x, pv0[i].y), sA);
            sA = ffma2(make_float2(wv.z, wv.w), make_float2(pv0[i].z, pv0[i].w), sA);
            sB = ffma2(make_float2(wv.x, wv.y), make_float2(pv1[i].x, pv1[i].y), sB);
            sB = ffma2(make_float2(wv.z, wv.w), make_float2(pv1[i].z, pv1[i].w), sB);
        }
        float tA = sA.x + sA.y, tB = sB.x + sB.y;
        #pragma unroll
        for (int off = 16; off > 0; off >>= 1) {
            tA += __shfl_xor_sync(0xffffffffu, tA, off);
            tB += __shfl_xor_sync(0xffffffffu, tB, off);
        }
        if (lane == j0) { my0 = tA; my1 = tB; }
    }

    if (lane < 8) {
        int j = jg * 8 + lane;
        float bj = b_out[j];
        out[(long)r0 * D_ + j] = bj + my0;
        out[(long)r1 * D_ + j] = bj + my1;
    }
}

// ======================================================================
extern "C" void kernel_launch(void* const* d_in, const int* in_sizes, int n_in,
                              void* d_out, int out_size)
{
    const float* x       = (const float*)d_in[0];
    const int*   mask    = (const int*)  d_in[1];
    const float* queries = (const float*)d_in[2];
    const float* w_out   = (const float*)d_in[3];
    const float* b_out   = (const float*)d_in[4];
    float* out = (float*)d_out;

    cudaFuncSetAttribute((const void*)attn_main,
                         cudaFuncAttributeMaxDynamicSharedMemorySize, SMEM_BYTES);

    // zero the atomic accumulators via graph memset nodes
    void* p_pool = nullptr; void* p_lsum = nullptr;
    cudaGetSymbolAddress(&p_pool, g_pool);
    cudaGetSymbolAddress(&p_lsum, g_lsum);
    cudaMemsetAsync(p_pool, 0, sizeof(float) * B_ * K_ * D_);
    cudaMemsetAsync(p_lsum, 0, sizeof(float) * B_ * K_ * H_);

    attn_main<<<G_, NTHR_, SMEM_BYTES>>>(x, mask, queries);
    epi_k<<<256, 256>>>(w_out, b_out, out);
}